// round 2
// baseline (speedup 1.0000x reference)
#include <cuda_runtime.h>
#include <cstdint>

// x:     [B=4, N=64,   D=1024] fp32
// cache: [B=4, S=8192, D=1024] fp32
// out:   [B=4, S=8192, D=1024] fp32
// out[b, s, :] = cache[b, s+N, :]   for s <  S-N   (bulk: src = dst + N*D within batch)
// out[b, s, :] = x[b, s-(S-N), :]   for s >= S-N   (tail)

static constexpr int B  = 4;
static constexpr int S  = 8192;
static constexpr int D  = 1024;
static constexpr int N  = 64;
static constexpr int D4 = D / 4;                      // 256 float4 per row
static constexpr int ROW4_PER_B  = S * D4;            // 2,097,152 float4 per batch
static constexpr int BULK4_PER_B = (S - N) * D4;      // 2,080,768 float4 per batch
static constexpr int SHIFT4      = N * D4;            // 16,384 float4
static constexpr int TAIL4_PER_B = N * D4;            // 16,384 float4 per batch

static constexpr int THREADS = 256;
static constexpr int VPT     = 4;                     // float4 per thread
static constexpr int CHUNK   = THREADS * VPT;         // 1024 float4 per CTA

// Bulk: grid (BULK4_PER_B / CHUNK = 2032, B). Each CTA copies 1024 contiguous float4.
__global__ __launch_bounds__(THREADS)
void roll_bulk_kernel(const float4* __restrict__ cache4, float4* __restrict__ out4)
{
    const int b    = blockIdx.y;
    const int base = blockIdx.x * CHUNK + threadIdx.x;     // within-batch float4 index
    const float4* src = cache4 + (size_t)b * ROW4_PER_B + SHIFT4 + base;
    float4*       dst = out4   + (size_t)b * ROW4_PER_B + base;

    float4 v0 = __ldcs(src + 0 * THREADS);
    float4 v1 = __ldcs(src + 1 * THREADS);
    float4 v2 = __ldcs(src + 2 * THREADS);
    float4 v3 = __ldcs(src + 3 * THREADS);
    __stcs(dst + 0 * THREADS, v0);
    __stcs(dst + 1 * THREADS, v1);
    __stcs(dst + 2 * THREADS, v2);
    __stcs(dst + 3 * THREADS, v3);
}

// Tail: grid (TAIL4_PER_B / CHUNK = 16, B). Copies x into the last N rows.
__global__ __launch_bounds__(THREADS)
void roll_tail_kernel(const float4* __restrict__ x4, float4* __restrict__ out4)
{
    const int b    = blockIdx.y;
    const int base = blockIdx.x * CHUNK + threadIdx.x;     // within-batch tail float4 index
    const float4* src = x4   + (size_t)b * TAIL4_PER_B + base;
    float4*       dst = out4 + (size_t)b * ROW4_PER_B + BULK4_PER_B + base;

    float4 v0 = __ldcs(src + 0 * THREADS);
    float4 v1 = __ldcs(src + 1 * THREADS);
    float4 v2 = __ldcs(src + 2 * THREADS);
    float4 v3 = __ldcs(src + 3 * THREADS);
    __stcs(dst + 0 * THREADS, v0);
    __stcs(dst + 1 * THREADS, v1);
    __stcs(dst + 2 * THREADS, v2);
    __stcs(dst + 3 * THREADS, v3);
}

extern "C" void kernel_launch(void* const* d_in, const int* in_sizes, int n_in,
                              void* d_out, int out_size)
{
    const float4* x4     = (const float4*)d_in[0];
    const float4* cache4 = (const float4*)d_in[1];
    float4* out4 = (float4*)d_out;

    dim3 bulk_grid(BULK4_PER_B / CHUNK, B);   // (2032, 4)
    dim3 tail_grid(TAIL4_PER_B / CHUNK, B);   // (16, 4)
    roll_bulk_kernel<<<bulk_grid, THREADS>>>(cache4, out4);
    roll_tail_kernel<<<tail_grid, THREADS>>>(x4, out4);
}

// round 3
// speedup vs baseline: 1.0538x; 1.0538x over previous
#include <cuda_runtime.h>
#include <cstdint>

// x:     [B=4, N=64,   D=1024] fp32
// cache: [B=4, S=8192, D=1024] fp32
// out:   [B=4, S=8192, D=1024] fp32
// out[b, s, :] = cache[b, s+N, :]   for s <  S-N   (bulk)
// out[b, s, :] = x[b, s-(S-N), :]   for s >= S-N   (tail)

static constexpr int B  = 4;
static constexpr int S  = 8192;
static constexpr int D  = 1024;
static constexpr int N  = 64;
static constexpr int D4 = D / 4;                      // 256 float4 per row
static constexpr int ROW4_PER_B  = S * D4;            // 2,097,152 float4 per batch
static constexpr int BULK4_PER_B = (S - N) * D4;      // 2,080,768 float4 per batch
static constexpr int SHIFT4      = N * D4;            // 16,384 float4
static constexpr int TAIL4_PER_B = N * D4;            // 16,384 float4 per batch

static constexpr int THREADS = 256;
static constexpr int VPT     = 4;                     // float4 per thread
static constexpr int CHUNK   = THREADS * VPT;         // 1024 float4 per CTA
static constexpr int BULK_BLOCKS = BULK4_PER_B / CHUNK;  // 2032
static constexpr int TAIL_BLOCKS = TAIL4_PER_B / CHUNK;  // 16
static constexpr int BLOCKS_X    = BULK_BLOCKS + TAIL_BLOCKS;  // 2048

__global__ __launch_bounds__(THREADS)
void roll_fused_kernel(const float4* __restrict__ x4,
                       const float4* __restrict__ cache4,
                       float4* __restrict__ out4)
{
    const int b   = blockIdx.y;
    const int bx  = blockIdx.x;
    const int tid = threadIdx.x;

    const float4* src;
    float4*       dst;
    if (bx < BULK_BLOCKS) {
        // bulk: out[b, base] = cache[b, base + SHIFT4]
        const int base = bx * CHUNK + tid;
        src = cache4 + (size_t)b * ROW4_PER_B + SHIFT4 + base;
        dst = out4   + (size_t)b * ROW4_PER_B + base;
    } else {
        // tail: out[b, BULK4 + tbase] = x[b, tbase]
        const int tbase = (bx - BULK_BLOCKS) * CHUNK + tid;
        src = x4   + (size_t)b * TAIL4_PER_B + tbase;
        dst = out4 + (size_t)b * ROW4_PER_B + BULK4_PER_B + tbase;
    }

    float4 v0 = __ldcs(src + 0 * THREADS);
    float4 v1 = __ldcs(src + 1 * THREADS);
    float4 v2 = __ldcs(src + 2 * THREADS);
    float4 v3 = __ldcs(src + 3 * THREADS);
    __stcs(dst + 0 * THREADS, v0);
    __stcs(dst + 1 * THREADS, v1);
    __stcs(dst + 2 * THREADS, v2);
    __stcs(dst + 3 * THREADS, v3);
}

extern "C" void kernel_launch(void* const* d_in, const int* in_sizes, int n_in,
                              void* d_out, int out_size)
{
    const float4* x4     = (const float4*)d_in[0];
    const float4* cache4 = (const float4*)d_in[1];
    float4* out4 = (float4*)d_out;

    dim3 grid(BLOCKS_X, B);   // (2048, 4) = 8192 CTAs
    roll_fused_kernel<<<grid, THREADS>>>(x4, cache4, out4);
}